// round 3
// baseline (speedup 1.0000x reference)
#include <cuda_runtime.h>
#include <math.h>

#define D_MODEL 1024
#define NTOK    8192   // B*T
#define HEADS   16
#define HD      64
#define TSEQ    2048
#define BATCH   4

#define PITCH   68     // smem row pitch (floats): multiple of 4 -> float4 aligned

// Scratch (no allocation allowed — device globals). 16B-aligned for float4.
__device__ __align__(16) float g_Q[NTOK * D_MODEL];
__device__ __align__(16) float g_K[NTOK * D_MODEL];
__device__ __align__(16) float g_V[NTOK * D_MODEL];
__device__ __align__(16) float g_A[NTOK * D_MODEL];

// ---------------------------------------------------------------------------
// SGEMM: C[M,N] = A[M,K] @ B[K,N] + bias[N]   (all row-major, fp32)
// 128x128 block tile, BK=8, 256 threads, 8x8 micro-tile split 4+4.
// ---------------------------------------------------------------------------
__global__ __launch_bounds__(256, 2)
void sgemm_bias_kernel(const float* __restrict__ A, const float* __restrict__ B,
                       const float* __restrict__ bias, float* __restrict__ C,
                       int M, int N, int K)
{
    __shared__ float As[8][128];
    __shared__ float Bs[8][128];

    const int tid  = threadIdx.x;
    const int bx   = blockIdx.x, by = blockIdx.y;
    const int tcol = tid & 15, trow = tid >> 4;

    const int aRow = tid >> 1,  aCol = (tid & 1) * 4;   // 128 x 8 tile of A
    const int bRow = tid >> 5,  bCol = (tid & 31) * 4;  // 8 x 128 tile of B

    const float* Ab = A + (size_t)by * 128 * K;
    const float* Bb = B + bx * 128;

    float acc[8][8];
#pragma unroll
    for (int i = 0; i < 8; i++)
#pragma unroll
        for (int j = 0; j < 8; j++) acc[i][j] = 0.f;

    for (int k0 = 0; k0 < K; k0 += 8) {
        float4 a4 = *(const float4*)(Ab + (size_t)aRow * K + k0 + aCol);
        As[aCol + 0][aRow] = a4.x;
        As[aCol + 1][aRow] = a4.y;
        As[aCol + 2][aRow] = a4.z;
        As[aCol + 3][aRow] = a4.w;
        *(float4*)&Bs[bRow][bCol] = *(const float4*)(Bb + (size_t)(k0 + bRow) * N + bCol);
        __syncthreads();

#pragma unroll
        for (int k = 0; k < 8; k++) {
            float4 m0 = *(const float4*)&As[k][trow * 4];
            float4 m1 = *(const float4*)&As[k][64 + trow * 4];
            float4 n0 = *(const float4*)&Bs[k][tcol * 4];
            float4 n1 = *(const float4*)&Bs[k][64 + tcol * 4];
            float rm[8] = {m0.x, m0.y, m0.z, m0.w, m1.x, m1.y, m1.z, m1.w};
            float rn[8] = {n0.x, n0.y, n0.z, n0.w, n1.x, n1.y, n1.z, n1.w};
#pragma unroll
            for (int i = 0; i < 8; i++)
#pragma unroll
                for (int j = 0; j < 8; j++) acc[i][j] += rm[i] * rn[j];
        }
        __syncthreads();
    }

#pragma unroll
    for (int ih = 0; ih < 2; ih++) {
#pragma unroll
        for (int i = 0; i < 4; i++) {
            int row = by * 128 + ih * 64 + trow * 4 + i;
#pragma unroll
            for (int jh = 0; jh < 2; jh++) {
                int col = bx * 128 + jh * 64 + tcol * 4;
                float4 o;
                o.x = acc[ih * 4 + i][jh * 4 + 0] + bias[col + 0];
                o.y = acc[ih * 4 + i][jh * 4 + 1] + bias[col + 1];
                o.z = acc[ih * 4 + i][jh * 4 + 2] + bias[col + 2];
                o.w = acc[ih * 4 + i][jh * 4 + 3] + bias[col + 3];
                *(float4*)(C + (size_t)row * N + col) = o;
            }
        }
    }
}

// ---------------------------------------------------------------------------
// Flash attention (fp32, online softmax). One block = 64 query rows of one
// (b,h). Tiles of 64 keys. Head h occupies gmem columns [h*64, h*64+64).
// smem (dynamic, pitch 68 floats): Qs[64][68], KsT[64][68] (d-major),
// Vs[64][68], Ps[64][68]  -> 4*64*68*4 = 69632 bytes
// ---------------------------------------------------------------------------
__global__ __launch_bounds__(256, 2)
void attention_kernel(const float* __restrict__ Q, const float* __restrict__ K,
                      const float* __restrict__ V, float* __restrict__ O)
{
    extern __shared__ float sm[];
    float* Qs  = sm;                 // [64][PITCH]
    float* KsT = sm + 64 * PITCH;    // [64][PITCH], indexed [d][key]
    float* Vs  = sm + 2 * 64 * PITCH;
    float* Ps  = sm + 3 * 64 * PITCH;

    const int tid = threadIdx.x;
    const int tx  = tid & 15, ty = tid >> 4;
    const int qt = blockIdx.x, h = blockIdx.y, b = blockIdx.z;

    const size_t base = ((size_t)b * TSEQ) * D_MODEL + (size_t)h * HD;
    const float* Qb = Q + base + (size_t)qt * 64 * D_MODEL;
    const float* Kb = K + base;
    const float* Vb = V + base;

    // Load Q tile (64 x 64)
#pragma unroll
    for (int it = 0; it < 4; it++) {
        int i = tid + it * 256;
        int r = i >> 4, c = (i & 15) * 4;
        *(float4*)&Qs[r * PITCH + c] = *(const float4*)(Qb + (size_t)r * D_MODEL + c);
    }

    float o[4][4];
    float m_i[4], l_i[4];
#pragma unroll
    for (int i = 0; i < 4; i++) {
        m_i[i] = -1e30f; l_i[i] = 0.f;
#pragma unroll
        for (int j = 0; j < 4; j++) o[i][j] = 0.f;
    }

    for (int j0 = 0; j0 < TSEQ; j0 += 64) {
        __syncthreads();  // protect Ps/Vs/KsT (and first-iter Qs) before overwrite
        // Load K (transposed to d-major) and V tiles
#pragma unroll
        for (int it = 0; it < 4; it++) {
            int i = tid + it * 256;
            int r = i >> 4, c = (i & 15) * 4;
            float4 k4 = *(const float4*)(Kb + (size_t)(j0 + r) * D_MODEL + c);
            KsT[(c + 0) * PITCH + r] = k4.x;
            KsT[(c + 1) * PITCH + r] = k4.y;
            KsT[(c + 2) * PITCH + r] = k4.z;
            KsT[(c + 3) * PITCH + r] = k4.w;
            *(float4*)&Vs[r * PITCH + c] = *(const float4*)(Vb + (size_t)(j0 + r) * D_MODEL + c);
        }
        __syncthreads();

        // S = Q K^T (each thread: rows ty*4+i, keys tx*4+j)
        float s[4][4];
#pragma unroll
        for (int i = 0; i < 4; i++)
#pragma unroll
            for (int j = 0; j < 4; j++) s[i][j] = 0.f;

#pragma unroll 8
        for (int d = 0; d < 64; d++) {
            float4 kv = *(const float4*)&KsT[d * PITCH + tx * 4];
#pragma unroll
            for (int i = 0; i < 4; i++) {
                float qv = Qs[(ty * 4 + i) * PITCH + d];
                s[i][0] += qv * kv.x;
                s[i][1] += qv * kv.y;
                s[i][2] += qv * kv.z;
                s[i][3] += qv * kv.w;
            }
        }

        // Online softmax update (keys for row i live across the 16 tx lanes)
#pragma unroll
        for (int i = 0; i < 4; i++) {
            float mx = -1e30f;
#pragma unroll
            for (int j = 0; j < 4; j++) { s[i][j] *= 0.125f; mx = fmaxf(mx, s[i][j]); }
#pragma unroll
            for (int off = 8; off; off >>= 1)
                mx = fmaxf(mx, __shfl_xor_sync(0xffffffffu, mx, off));
            float mnew = fmaxf(m_i[i], mx);
            float fac  = __expf(m_i[i] - mnew);
            m_i[i] = mnew;
            float rs = 0.f;
#pragma unroll
            for (int j = 0; j < 4; j++) {
                float p = __expf(s[i][j] - mnew);
                s[i][j] = p; rs += p;
            }
#pragma unroll
            for (int off = 8; off; off >>= 1)
                rs += __shfl_xor_sync(0xffffffffu, rs, off);
            l_i[i] = l_i[i] * fac + rs;
#pragma unroll
            for (int j = 0; j < 4; j++) o[i][j] *= fac;
            *(float4*)&Ps[(ty * 4 + i) * PITCH + tx * 4] =
                make_float4(s[i][0], s[i][1], s[i][2], s[i][3]);
        }
        __syncthreads();

        // O += P V  (each thread: rows ty*4+i, out cols tx*4+j)
#pragma unroll 8
        for (int c = 0; c < 64; c++) {
            float4 vv = *(const float4*)&Vs[c * PITCH + tx * 4];
#pragma unroll
            for (int i = 0; i < 4; i++) {
                float p = Ps[(ty * 4 + i) * PITCH + c];
                o[i][0] += p * vv.x;
                o[i][1] += p * vv.y;
                o[i][2] += p * vv.z;
                o[i][3] += p * vv.w;
            }
        }
    }

    // Epilogue: normalize and store
    float* Ob = O + base + (size_t)qt * 64 * D_MODEL;
#pragma unroll
    for (int i = 0; i < 4; i++) {
        float inv = 1.f / l_i[i];
        float4 r = make_float4(o[i][0] * inv, o[i][1] * inv, o[i][2] * inv, o[i][3] * inv);
        *(float4*)(Ob + (size_t)(ty * 4 + i) * D_MODEL + tx * 4) = r;
    }
}

// ---------------------------------------------------------------------------
// Launch. Input order (reference signature):
// 0:q 1:k 2:v 3:W_q 4:b_q 5:W_k 6:b_k 7:W_v 8:b_v 9:W_o 10:b_o
// ---------------------------------------------------------------------------
extern "C" void kernel_launch(void* const* d_in, const int* in_sizes, int n_in,
                              void* d_out, int out_size)
{
    (void)in_sizes; (void)n_in; (void)out_size;
    const float* q   = (const float*)d_in[0];
    const float* k   = (const float*)d_in[1];
    const float* v   = (const float*)d_in[2];
    const float* W_q = (const float*)d_in[3];
    const float* b_q = (const float*)d_in[4];
    const float* W_k = (const float*)d_in[5];
    const float* b_k = (const float*)d_in[6];
    const float* W_v = (const float*)d_in[7];
    const float* b_v = (const float*)d_in[8];
    const float* W_o = (const float*)d_in[9];
    const float* b_o = (const float*)d_in[10];
    float* out = (float*)d_out;

    float *gQ, *gK, *gV, *gA;
    cudaGetSymbolAddress((void**)&gQ, g_Q);
    cudaGetSymbolAddress((void**)&gK, g_K);
    cudaGetSymbolAddress((void**)&gV, g_V);
    cudaGetSymbolAddress((void**)&gA, g_A);

    dim3 gridP(D_MODEL / 128, NTOK / 128);  // (8, 64)

    sgemm_bias_kernel<<<gridP, 256>>>(q, W_q, b_q, gQ, NTOK, D_MODEL, D_MODEL);
    sgemm_bias_kernel<<<gridP, 256>>>(k, W_k, b_k, gK, NTOK, D_MODEL, D_MODEL);
    sgemm_bias_kernel<<<gridP, 256>>>(v, W_v, b_v, gV, NTOK, D_MODEL, D_MODEL);

    cudaFuncSetAttribute(attention_kernel,
                         cudaFuncAttributeMaxDynamicSharedMemorySize, 69632);
    attention_kernel<<<dim3(TSEQ / 64, HEADS, BATCH), 256, 69632>>>(gQ, gK, gV, gA);

    sgemm_bias_kernel<<<gridP, 256>>>(gA, W_o, b_o, out, NTOK, D_MODEL, D_MODEL);
}

// round 4
// speedup vs baseline: 1.3680x; 1.3680x over previous
#include <cuda_runtime.h>
#include <math.h>
#include <stdint.h>

#define D_MODEL 1024
#define NTOK    8192   // B*T
#define HEADS   16
#define HD      64
#define TSEQ    2048
#define BATCH   4

#define PITCH   68     // attention smem row pitch (floats)

// GEMM tiling
#define BM 128
#define BN 128
#define BKT 16
#define APAD 20        // As row pitch (floats) -> conflict-free A fragment LDS
#define BPAD 136       // Bs row pitch (floats) -> conflict-free B fragment LDS

// Scratch (no allocation allowed — device globals). 16B-aligned for float4.
__device__ __align__(16) float g_Q[NTOK * D_MODEL];
__device__ __align__(16) float g_K[NTOK * D_MODEL];
__device__ __align__(16) float g_V[NTOK * D_MODEL];
__device__ __align__(16) float g_A[NTOK * D_MODEL];

__device__ __forceinline__ float tf32r(float x) {
    uint32_t u;
    asm("cvt.rna.tf32.f32 %0, %1;" : "=r"(u) : "f"(x));
    return __uint_as_float(u);
}

__device__ __forceinline__ void mma_tf32(float* c, const uint32_t* a, const uint32_t* b) {
    asm volatile(
        "mma.sync.aligned.m16n8k8.row.col.f32.tf32.tf32.f32 "
        "{%0,%1,%2,%3}, {%4,%5,%6,%7}, {%8,%9}, {%0,%1,%2,%3};\n"
        : "+f"(c[0]), "+f"(c[1]), "+f"(c[2]), "+f"(c[3])
        : "r"(a[0]), "r"(a[1]), "r"(a[2]), "r"(a[3]), "r"(b[0]), "r"(b[1]));
}

// ---------------------------------------------------------------------------
// TF32 tensor-core GEMM: C[M,N] = A[M,K] @ B[K,N] + bias[N]  (row-major fp32)
// 128x128 block, BK=16, 256 threads = 8 warps (2x4), warp tile 64x32.
// Register-staged single-buffer pipeline: prefetch next global tile during MMA.
// ---------------------------------------------------------------------------
__global__ __launch_bounds__(256, 2)
void gemm_tf32_bias(const float* __restrict__ A, const float* __restrict__ B,
                    const float* __restrict__ bias, float* __restrict__ C,
                    int M, int N, int K)
{
    __shared__ float As[BM * APAD];   // [row][k]
    __shared__ float Bs[BKT * BPAD];  // [k][n]

    const int tid  = threadIdx.x;
    const int warp = tid >> 5, lane = tid & 31;
    const int g = lane >> 2, t = lane & 3;       // groupID, tid-in-group
    const int wm = (warp >> 2) * 64;             // warp row offset
    const int wn = (warp & 3) * 32;              // warp col offset

    const int bx = blockIdx.x, by = blockIdx.y;
    const float* Ab = A + (size_t)by * BM * K;
    const float* Bb = B + bx * BN;

    // global load assignment (8 floats / thread / matrix / stage)
    const int arow = tid >> 1, acol = (tid & 1) * 8;   // A: 128 x 16
    const int brow = tid >> 4, bcol = (tid & 15) * 8;  // B: 16 x 128

    float4 pa0 = *(const float4*)(Ab + (size_t)arow * K + acol);
    float4 pa1 = *(const float4*)(Ab + (size_t)arow * K + acol + 4);
    float4 pb0 = *(const float4*)(Bb + (size_t)brow * N + bcol);
    float4 pb1 = *(const float4*)(Bb + (size_t)brow * N + bcol + 4);

    float acc[4][4][4];
#pragma unroll
    for (int mt = 0; mt < 4; mt++)
#pragma unroll
        for (int nt = 0; nt < 4; nt++)
#pragma unroll
            for (int i = 0; i < 4; i++) acc[mt][nt][i] = 0.f;

    for (int k0 = 0; k0 < K; k0 += BKT) {
        // commit staged registers to smem (convert to tf32)
        float* ad = As + arow * APAD + acol;
        ad[0] = tf32r(pa0.x); ad[1] = tf32r(pa0.y); ad[2] = tf32r(pa0.z); ad[3] = tf32r(pa0.w);
        ad[4] = tf32r(pa1.x); ad[5] = tf32r(pa1.y); ad[6] = tf32r(pa1.z); ad[7] = tf32r(pa1.w);
        float* bd = Bs + brow * BPAD + bcol;
        bd[0] = tf32r(pb0.x); bd[1] = tf32r(pb0.y); bd[2] = tf32r(pb0.z); bd[3] = tf32r(pb0.w);
        bd[4] = tf32r(pb1.x); bd[5] = tf32r(pb1.y); bd[6] = tf32r(pb1.z); bd[7] = tf32r(pb1.w);
        __syncthreads();

        // prefetch next stage (latency hidden behind MMA work below)
        if (k0 + BKT < K) {
            pa0 = *(const float4*)(Ab + (size_t)arow * K + k0 + BKT + acol);
            pa1 = *(const float4*)(Ab + (size_t)arow * K + k0 + BKT + acol + 4);
            pb0 = *(const float4*)(Bb + (size_t)(k0 + BKT + brow) * N + bcol);
            pb1 = *(const float4*)(Bb + (size_t)(k0 + BKT + brow) * N + bcol + 4);
        }

#pragma unroll
        for (int kk = 0; kk < BKT; kk += 8) {
            uint32_t af[4][4];
#pragma unroll
            for (int mt = 0; mt < 4; mt++) {
                const float* ap = As + (wm + mt * 16 + g) * APAD + kk + t;
                af[mt][0] = __float_as_uint(ap[0]);
                af[mt][1] = __float_as_uint(ap[8 * APAD]);
                af[mt][2] = __float_as_uint(ap[4]);
                af[mt][3] = __float_as_uint(ap[8 * APAD + 4]);
            }
            uint32_t bf[4][2];
#pragma unroll
            for (int nt = 0; nt < 4; nt++) {
                const float* bp = Bs + (kk + t) * BPAD + wn + nt * 8 + g;
                bf[nt][0] = __float_as_uint(bp[0]);
                bf[nt][1] = __float_as_uint(bp[4 * BPAD]);
            }
#pragma unroll
            for (int mt = 0; mt < 4; mt++)
#pragma unroll
                for (int nt = 0; nt < 4; nt++)
                    mma_tf32(acc[mt][nt], af[mt], bf[nt]);
        }
        __syncthreads();
    }

    // epilogue: bias + store
#pragma unroll
    for (int mt = 0; mt < 4; mt++) {
        int row0 = by * BM + wm + mt * 16 + g;
#pragma unroll
        for (int nt = 0; nt < 4; nt++) {
            int col = bx * BN + wn + nt * 8 + 2 * t;
            float b0 = bias[col], b1 = bias[col + 1];
            float2 r0 = make_float2(acc[mt][nt][0] + b0, acc[mt][nt][1] + b1);
            float2 r1 = make_float2(acc[mt][nt][2] + b0, acc[mt][nt][3] + b1);
            *(float2*)(C + (size_t)row0 * N + col) = r0;
            *(float2*)(C + (size_t)(row0 + 8) * N + col) = r1;
        }
    }
}

// ---------------------------------------------------------------------------
// Flash attention (fp32, online softmax) — unchanged from passing R3 kernel.
// ---------------------------------------------------------------------------
__global__ __launch_bounds__(256, 2)
void attention_kernel(const float* __restrict__ Q, const float* __restrict__ K,
                      const float* __restrict__ V, float* __restrict__ O)
{
    extern __shared__ float sm[];
    float* Qs  = sm;                 // [64][PITCH]
    float* KsT = sm + 64 * PITCH;    // [64][PITCH], indexed [d][key]
    float* Vs  = sm + 2 * 64 * PITCH;
    float* Ps  = sm + 3 * 64 * PITCH;

    const int tid = threadIdx.x;
    const int tx  = tid & 15, ty = tid >> 4;
    const int qt = blockIdx.x, h = blockIdx.y, b = blockIdx.z;

    const size_t base = ((size_t)b * TSEQ) * D_MODEL + (size_t)h * HD;
    const float* Qb = Q + base + (size_t)qt * 64 * D_MODEL;
    const float* Kb = K + base;
    const float* Vb = V + base;

#pragma unroll
    for (int it = 0; it < 4; it++) {
        int i = tid + it * 256;
        int r = i >> 4, c = (i & 15) * 4;
        *(float4*)&Qs[r * PITCH + c] = *(const float4*)(Qb + (size_t)r * D_MODEL + c);
    }

    float o[4][4];
    float m_i[4], l_i[4];
#pragma unroll
    for (int i = 0; i < 4; i++) {
        m_i[i] = -1e30f; l_i[i] = 0.f;
#pragma unroll
        for (int j = 0; j < 4; j++) o[i][j] = 0.f;
    }

    for (int j0 = 0; j0 < TSEQ; j0 += 64) {
        __syncthreads();
#pragma unroll
        for (int it = 0; it < 4; it++) {
            int i = tid + it * 256;
            int r = i >> 4, c = (i & 15) * 4;
            float4 k4 = *(const float4*)(Kb + (size_t)(j0 + r) * D_MODEL + c);
            KsT[(c + 0) * PITCH + r] = k4.x;
            KsT[(c + 1) * PITCH + r] = k4.y;
            KsT[(c + 2) * PITCH + r] = k4.z;
            KsT[(c + 3) * PITCH + r] = k4.w;
            *(float4*)&Vs[r * PITCH + c] = *(const float4*)(Vb + (size_t)(j0 + r) * D_MODEL + c);
        }
        __syncthreads();

        float s[4][4];
#pragma unroll
        for (int i = 0; i < 4; i++)
#pragma unroll
            for (int j = 0; j < 4; j++) s[i][j] = 0.f;

#pragma unroll 8
        for (int d = 0; d < 64; d++) {
            float4 kv = *(const float4*)&KsT[d * PITCH + tx * 4];
#pragma unroll
            for (int i = 0; i < 4; i++) {
                float qv = Qs[(ty * 4 + i) * PITCH + d];
                s[i][0] += qv * kv.x;
                s[i][1] += qv * kv.y;
                s[i][2] += qv * kv.z;
                s[i][3] += qv * kv.w;
            }
        }

#pragma unroll
        for (int i = 0; i < 4; i++) {
            float mx = -1e30f;
#pragma unroll
            for (int j = 0; j < 4; j++) { s[i][j] *= 0.125f; mx = fmaxf(mx, s[i][j]); }
#pragma unroll
            for (int off = 8; off; off >>= 1)
                mx = fmaxf(mx, __shfl_xor_sync(0xffffffffu, mx, off));
            float mnew = fmaxf(m_i[i], mx);
            float fac  = __expf(m_i[i] - mnew);
            m_i[i] = mnew;
            float rs = 0.f;
#pragma unroll
            for (int j = 0; j < 4; j++) {
                float p = __expf(s[i][j] - mnew);
                s[i][j] = p; rs += p;
            }
#pragma unroll
            for (int off = 8; off; off >>= 1)
                rs += __shfl_xor_sync(0xffffffffu, rs, off);
            l_i[i] = l_i[i] * fac + rs;
#pragma unroll
            for (int j = 0; j < 4; j++) o[i][j] *= fac;
            *(float4*)&Ps[(ty * 4 + i) * PITCH + tx * 4] =
                make_float4(s[i][0], s[i][1], s[i][2], s[i][3]);
        }
        __syncthreads();

#pragma unroll 8
        for (int c = 0; c < 64; c++) {
            float4 vv = *(const float4*)&Vs[c * PITCH + tx * 4];
#pragma unroll
            for (int i = 0; i < 4; i++) {
                float p = Ps[(ty * 4 + i) * PITCH + c];
                o[i][0] += p * vv.x;
                o[i][1] += p * vv.y;
                o[i][2] += p * vv.z;
                o[i][3] += p * vv.w;
            }
        }
    }

    float* Ob = O + base + (size_t)qt * 64 * D_MODEL;
#pragma unroll
    for (int i = 0; i < 4; i++) {
        float inv = 1.f / l_i[i];
        float4 r = make_float4(o[i][0] * inv, o[i][1] * inv, o[i][2] * inv, o[i][3] * inv);
        *(float4*)(Ob + (size_t)(ty * 4 + i) * D_MODEL + tx * 4) = r;
    }
}

// ---------------------------------------------------------------------------
// Launch. Input order:
// 0:q 1:k 2:v 3:W_q 4:b_q 5:W_k 6:b_k 7:W_v 8:b_v 9:W_o 10:b_o
// ---------------------------------------------------------------------------
extern "C" void kernel_launch(void* const* d_in, const int* in_sizes, int n_in,
                              void* d_out, int out_size)
{
    (void)in_sizes; (void)n_in; (void)out_size;
    const float* q   = (const float*)d_in[0];
    const float* k   = (const float*)d_in[1];
    const float* v   = (const float*)d_in[2];
    const float* W_q = (const float*)d_in[3];
    const float* b_q = (const float*)d_in[4];
    const float* W_k = (const float*)d_in[5];
    const float* b_k = (const float*)d_in[6];
    const float* W_v = (const float*)d_in[7];
    const float* b_v = (const float*)d_in[8];
    const float* W_o = (const float*)d_in[9];
    const float* b_o = (const float*)d_in[10];
    float* out = (float*)d_out;

    float *gQ, *gK, *gV, *gA;
    cudaGetSymbolAddress((void**)&gQ, g_Q);
    cudaGetSymbolAddress((void**)&gK, g_K);
    cudaGetSymbolAddress((void**)&gV, g_V);
    cudaGetSymbolAddress((void**)&gA, g_A);

    dim3 gridP(D_MODEL / BN, NTOK / BM);  // (8, 64)

    gemm_tf32_bias<<<gridP, 256>>>(q, W_q, b_q, gQ, NTOK, D_MODEL, D_MODEL);
    gemm_tf32_bias<<<gridP, 256>>>(k, W_k, b_k, gK, NTOK, D_MODEL, D_MODEL);
    gemm_tf32_bias<<<gridP, 256>>>(v, W_v, b_v, gV, NTOK, D_MODEL, D_MODEL);

    cudaFuncSetAttribute(attention_kernel,
                         cudaFuncAttributeMaxDynamicSharedMemorySize, 69632);
    attention_kernel<<<dim3(TSEQ / 64, HEADS, BATCH), 256, 69632>>>(gQ, gK, gV, gA);

    gemm_tf32_bias<<<gridP, 256>>>(gA, W_o, b_o, out, NTOK, D_MODEL, D_MODEL);
}

// round 6
// speedup vs baseline: 2.1733x; 1.5887x over previous
#include <cuda_runtime.h>
#include <cuda_bf16.h>
#include <math.h>
#include <stdint.h>
#include <string.h>

#define D_MODEL 1024
#define NTOK    8192   // B*T
#define HEADS   16
#define HD      64
#define TSEQ    2048
#define BATCH   4

// GEMM tiling
#define BM 128
#define BN 128
#define BKT 16
#define APAD 20
#define BPAD 136

// Attention bf16 smem pitch (bf16 elements). 72*2B=144B rows; 36 words.
#define PB   72
#define PB32 36

// Scratch (no allocation allowed — device globals). 16B-aligned.
__device__ __align__(16) float g_Q[NTOK * D_MODEL];
__device__ __align__(16) float g_K[NTOK * D_MODEL];
__device__ __align__(16) float g_V[NTOK * D_MODEL];
__device__ __align__(16) float g_A[NTOK * D_MODEL];

__device__ __forceinline__ float tf32r(float x) {
    uint32_t u;
    asm("cvt.rna.tf32.f32 %0, %1;" : "=r"(u) : "f"(x));
    return __uint_as_float(u);
}

__device__ __forceinline__ void mma_tf32(float* c, const uint32_t* a, const uint32_t* b) {
    asm volatile(
        "mma.sync.aligned.m16n8k8.row.col.f32.tf32.tf32.f32 "
        "{%0,%1,%2,%3}, {%4,%5,%6,%7}, {%8,%9}, {%0,%1,%2,%3};\n"
        : "+f"(c[0]), "+f"(c[1]), "+f"(c[2]), "+f"(c[3])
        : "r"(a[0]), "r"(a[1]), "r"(a[2]), "r"(a[3]), "r"(b[0]), "r"(b[1]));
}

__device__ __forceinline__ void mma_bf16(float* c, const uint32_t* a, uint32_t b0, uint32_t b1) {
    asm volatile(
        "mma.sync.aligned.m16n8k16.row.col.f32.bf16.bf16.f32 "
        "{%0,%1,%2,%3}, {%4,%5,%6,%7}, {%8,%9}, {%0,%1,%2,%3};\n"
        : "+f"(c[0]), "+f"(c[1]), "+f"(c[2]), "+f"(c[3])
        : "r"(a[0]), "r"(a[1]), "r"(a[2]), "r"(a[3]), "r"(b0), "r"(b1));
}

// split fp32 -> bf16 hi + bf16 lo  (hi+lo reproduces ~16 mantissa bits)
__device__ __forceinline__ void bsplit(float x, __nv_bfloat16& h, __nv_bfloat16& l) {
    h = __float2bfloat16(x);
    l = __float2bfloat16(x - __bfloat162float(h));
}

// pack two bf16 into one 32-bit word (lo in low half, hi in high half)
__device__ __forceinline__ uint32_t pack2(__nv_bfloat16 lo, __nv_bfloat16 hi) {
    __nv_bfloat162 p = __halves2bfloat162(lo, hi);
    uint32_t u;
    memcpy(&u, &p, 4);
    return u;
}

// ---------------------------------------------------------------------------
// TF32 tensor-core GEMM (unchanged from R4 passing kernel)
// ---------------------------------------------------------------------------
__global__ __launch_bounds__(256, 2)
void gemm_tf32_bias(const float* __restrict__ A, const float* __restrict__ B,
                    const float* __restrict__ bias, float* __restrict__ C,
                    int M, int N, int K)
{
    __shared__ float As[BM * APAD];
    __shared__ float Bs[BKT * BPAD];

    const int tid  = threadIdx.x;
    const int warp = tid >> 5, lane = tid & 31;
    const int g = lane >> 2, t = lane & 3;
    const int wm = (warp >> 2) * 64;
    const int wn = (warp & 3) * 32;

    const int bx = blockIdx.x, by = blockIdx.y;
    const float* Ab = A + (size_t)by * BM * K;
    const float* Bb = B + bx * BN;

    const int arow = tid >> 1, acol = (tid & 1) * 8;
    const int brow = tid >> 4, bcol = (tid & 15) * 8;

    float4 pa0 = *(const float4*)(Ab + (size_t)arow * K + acol);
    float4 pa1 = *(const float4*)(Ab + (size_t)arow * K + acol + 4);
    float4 pb0 = *(const float4*)(Bb + (size_t)brow * N + bcol);
    float4 pb1 = *(const float4*)(Bb + (size_t)brow * N + bcol + 4);

    float acc[4][4][4];
#pragma unroll
    for (int mt = 0; mt < 4; mt++)
#pragma unroll
        for (int nt = 0; nt < 4; nt++)
#pragma unroll
            for (int i = 0; i < 4; i++) acc[mt][nt][i] = 0.f;

    for (int k0 = 0; k0 < K; k0 += BKT) {
        float* ad = As + arow * APAD + acol;
        ad[0] = tf32r(pa0.x); ad[1] = tf32r(pa0.y); ad[2] = tf32r(pa0.z); ad[3] = tf32r(pa0.w);
        ad[4] = tf32r(pa1.x); ad[5] = tf32r(pa1.y); ad[6] = tf32r(pa1.z); ad[7] = tf32r(pa1.w);
        float* bd = Bs + brow * BPAD + bcol;
        bd[0] = tf32r(pb0.x); bd[1] = tf32r(pb0.y); bd[2] = tf32r(pb0.z); bd[3] = tf32r(pb0.w);
        bd[4] = tf32r(pb1.x); bd[5] = tf32r(pb1.y); bd[6] = tf32r(pb1.z); bd[7] = tf32r(pb1.w);
        __syncthreads();

        if (k0 + BKT < K) {
            pa0 = *(const float4*)(Ab + (size_t)arow * K + k0 + BKT + acol);
            pa1 = *(const float4*)(Ab + (size_t)arow * K + k0 + BKT + acol + 4);
            pb0 = *(const float4*)(Bb + (size_t)(k0 + BKT + brow) * N + bcol);
            pb1 = *(const float4*)(Bb + (size_t)(k0 + BKT + brow) * N + bcol + 4);
        }

#pragma unroll
        for (int kk = 0; kk < BKT; kk += 8) {
            uint32_t af[4][4];
#pragma unroll
            for (int mt = 0; mt < 4; mt++) {
                const float* ap = As + (wm + mt * 16 + g) * APAD + kk + t;
                af[mt][0] = __float_as_uint(ap[0]);
                af[mt][1] = __float_as_uint(ap[8 * APAD]);
                af[mt][2] = __float_as_uint(ap[4]);
                af[mt][3] = __float_as_uint(ap[8 * APAD + 4]);
            }
            uint32_t bf[4][2];
#pragma unroll
            for (int nt = 0; nt < 4; nt++) {
                const float* bp = Bs + (kk + t) * BPAD + wn + nt * 8 + g;
                bf[nt][0] = __float_as_uint(bp[0]);
                bf[nt][1] = __float_as_uint(bp[4 * BPAD]);
            }
#pragma unroll
            for (int mt = 0; mt < 4; mt++)
#pragma unroll
                for (int nt = 0; nt < 4; nt++)
                    mma_tf32(acc[mt][nt], af[mt], bf[nt]);
        }
        __syncthreads();
    }

#pragma unroll
    for (int mt = 0; mt < 4; mt++) {
        int row0 = by * BM + wm + mt * 16 + g;
#pragma unroll
        for (int nt = 0; nt < 4; nt++) {
            int col = bx * BN + wn + nt * 8 + 2 * t;
            float b0 = bias[col], b1 = bias[col + 1];
            float2 r0 = make_float2(acc[mt][nt][0] + b0, acc[mt][nt][1] + b1);
            float2 r1 = make_float2(acc[mt][nt][2] + b0, acc[mt][nt][3] + b1);
            *(float2*)(C + (size_t)row0 * N + col) = r0;
            *(float2*)(C + (size_t)(row0 + 8) * N + col) = r1;
        }
    }
}

// ---------------------------------------------------------------------------
// Flash attention with bf16x3 split tensor-core MMA (effective fp32 precision).
// Block: 128 threads = 4 warps; warp w owns 16 query rows, all 64 keys/tile.
// smem (bf16, pitch PB=72): Qh Ql Kh Kl Vth Vtl Ph Pl = 8 * 64*72*2 = 73728 B.
// Q pre-scaled by 1/8 and split once. K stored [key][d] (is col-major B op).
// V stored transposed [d][key]. P written from S frags as bf16x2 pairs.
// ---------------------------------------------------------------------------
#define OFF_QH 0
#define OFF_QL (64 * PB)
#define OFF_KH (2 * 64 * PB)
#define OFF_KL (3 * 64 * PB)
#define OFF_VH (4 * 64 * PB)
#define OFF_VL (5 * 64 * PB)
#define OFF_PH (6 * 64 * PB)
#define OFF_PL (7 * 64 * PB)
#define ATT_SMEM (8 * 64 * PB * 2)   // bytes = 73728

__global__ __launch_bounds__(128, 2)
void attention_bf16x3_kernel(const float* __restrict__ Q, const float* __restrict__ K,
                             const float* __restrict__ V, float* __restrict__ O)
{
    extern __shared__ __align__(16) __nv_bfloat16 sb[];
    __nv_bfloat16* Qh = sb + OFF_QH;
    __nv_bfloat16* Ql = sb + OFF_QL;
    __nv_bfloat16* Kh = sb + OFF_KH;
    __nv_bfloat16* Kl = sb + OFF_KL;
    __nv_bfloat16* Vh = sb + OFF_VH;   // transposed [d][key]
    __nv_bfloat16* Vl = sb + OFF_VL;
    __nv_bfloat16* Ph = sb + OFF_PH;
    __nv_bfloat16* Pl = sb + OFF_PL;

    const uint32_t* Qh32 = (const uint32_t*)Qh;
    const uint32_t* Ql32 = (const uint32_t*)Ql;
    const uint32_t* Kh32 = (const uint32_t*)Kh;
    const uint32_t* Kl32 = (const uint32_t*)Kl;
    const uint32_t* Vh32 = (const uint32_t*)Vh;
    const uint32_t* Vl32 = (const uint32_t*)Vl;
    uint32_t* Ph32 = (uint32_t*)Ph;
    uint32_t* Pl32 = (uint32_t*)Pl;

    const int tid  = threadIdx.x;
    const int warp = tid >> 5, lane = tid & 31;
    const int g = lane >> 2, t = lane & 3;
    const int row16 = warp * 16;

    const int qt = blockIdx.x, h = blockIdx.y, b = blockIdx.z;
    const size_t base = ((size_t)b * TSEQ) * D_MODEL + (size_t)h * HD;
    const float* Qb = Q + base + (size_t)qt * 64 * D_MODEL;
    const float* Kb = K + base;
    const float* Vb = V + base;

    // ---- Load + scale + split Q once (64x64) ----
#pragma unroll
    for (int it = 0; it < 8; it++) {
        int i = tid + it * 128;
        int r = i >> 4, c = (i & 15) * 4;
        float4 q4 = *(const float4*)(Qb + (size_t)r * D_MODEL + c);
        __nv_bfloat16 h0, h1, h2, h3, l0, l1, l2, l3;
        bsplit(q4.x * 0.125f, h0, l0); bsplit(q4.y * 0.125f, h1, l1);
        bsplit(q4.z * 0.125f, h2, l2); bsplit(q4.w * 0.125f, h3, l3);
        *(uint32_t*)&Qh[r * PB + c]     = pack2(h0, h1);
        *(uint32_t*)&Qh[r * PB + c + 2] = pack2(h2, h3);
        *(uint32_t*)&Ql[r * PB + c]     = pack2(l0, l1);
        *(uint32_t*)&Ql[r * PB + c + 2] = pack2(l2, l3);
    }

    // Per-thread state: O accum frags (8 d-tiles x 4), row stats for rows g,g+8
    float oacc[8][4];
#pragma unroll
    for (int j = 0; j < 8; j++)
#pragma unroll
        for (int i = 0; i < 4; i++) oacc[j][i] = 0.f;
    float m0 = -1e30f, m1 = -1e30f, l0s = 0.f, l1s = 0.f;

    // V lane mapping: row = 16*warp + (lane&15), col base selects by (lane>>4)
    const int vrow = row16 + (lane & 15);
    const int vcg  = lane >> 4;

    for (int j0 = 0; j0 < TSEQ; j0 += 64) {
        __syncthreads();  // previous tile's K/V reads complete

        // ---- Load + split K (coalesced), V (transposed) ----
#pragma unroll
        for (int it = 0; it < 8; it++) {
            int i = tid + it * 128;
            int r = i >> 4, c = (i & 15) * 4;
            float4 k4 = *(const float4*)(Kb + (size_t)(j0 + r) * D_MODEL + c);
            __nv_bfloat16 h0, h1, h2, h3, l0, l1, l2, l3;
            bsplit(k4.x, h0, l0); bsplit(k4.y, h1, l1);
            bsplit(k4.z, h2, l2); bsplit(k4.w, h3, l3);
            *(uint32_t*)&Kh[r * PB + c]     = pack2(h0, h1);
            *(uint32_t*)&Kh[r * PB + c + 2] = pack2(h2, h3);
            *(uint32_t*)&Kl[r * PB + c]     = pack2(l0, l1);
            *(uint32_t*)&Kl[r * PB + c + 2] = pack2(l2, l3);
        }
#pragma unroll
        for (int it = 0; it < 8; it++) {
            int c = (vcg + 2 * it) * 4;
            float4 v4 = *(const float4*)(Vb + (size_t)(j0 + vrow) * D_MODEL + c);
            __nv_bfloat16 hh, ll;
            bsplit(v4.x, hh, ll); Vh[(c + 0) * PB + vrow] = hh; Vl[(c + 0) * PB + vrow] = ll;
            bsplit(v4.y, hh, ll); Vh[(c + 1) * PB + vrow] = hh; Vl[(c + 1) * PB + vrow] = ll;
            bsplit(v4.z, hh, ll); Vh[(c + 2) * PB + vrow] = hh; Vl[(c + 2) * PB + vrow] = ll;
            bsplit(v4.w, hh, ll); Vh[(c + 3) * PB + vrow] = hh; Vl[(c + 3) * PB + vrow] = ll;
        }
        __syncthreads();

        // ---- S = Q K^T  (bf16x3: QhKh + QhKl + QlKh) ----
        float sacc[8][4];
#pragma unroll
        for (int j = 0; j < 8; j++)
#pragma unroll
            for (int i = 0; i < 4; i++) sacc[j][i] = 0.f;

#pragma unroll
        for (int kb = 0; kb < 64; kb += 16) {
            const int w0 = kb / 2 + t;  // uint32 word offset within row
            uint32_t qfh[4], qfl[4];
            qfh[0] = Qh32[(row16 + g) * PB32 + w0];
            qfh[1] = Qh32[(row16 + g + 8) * PB32 + w0];
            qfh[2] = Qh32[(row16 + g) * PB32 + w0 + 4];
            qfh[3] = Qh32[(row16 + g + 8) * PB32 + w0 + 4];
            qfl[0] = Ql32[(row16 + g) * PB32 + w0];
            qfl[1] = Ql32[(row16 + g + 8) * PB32 + w0];
            qfl[2] = Ql32[(row16 + g) * PB32 + w0 + 4];
            qfl[3] = Ql32[(row16 + g + 8) * PB32 + w0 + 4];
#pragma unroll
            for (int j = 0; j < 8; j++) {
                uint32_t kh0 = Kh32[(j * 8 + g) * PB32 + w0];
                uint32_t kh1 = Kh32[(j * 8 + g) * PB32 + w0 + 4];
                uint32_t kl0 = Kl32[(j * 8 + g) * PB32 + w0];
                uint32_t kl1 = Kl32[(j * 8 + g) * PB32 + w0 + 4];
                mma_bf16(sacc[j], qfh, kh0, kh1);
                mma_bf16(sacc[j], qfh, kl0, kl1);
                mma_bf16(sacc[j], qfl, kh0, kh1);
            }
        }

        // ---- Online softmax on fragments (rows g and g+8) ----
        float mx0 = -1e30f, mx1 = -1e30f;
#pragma unroll
        for (int j = 0; j < 8; j++) {
            mx0 = fmaxf(mx0, fmaxf(sacc[j][0], sacc[j][1]));
            mx1 = fmaxf(mx1, fmaxf(sacc[j][2], sacc[j][3]));
        }
        mx0 = fmaxf(mx0, __shfl_xor_sync(0xffffffffu, mx0, 1));
        mx0 = fmaxf(mx0, __shfl_xor_sync(0xffffffffu, mx0, 2));
        mx1 = fmaxf(mx1, __shfl_xor_sync(0xffffffffu, mx1, 1));
        mx1 = fmaxf(mx1, __shfl_xor_sync(0xffffffffu, mx1, 2));

        float mn0 = fmaxf(m0, mx0), mn1 = fmaxf(m1, mx1);
        float fac0 = __expf(m0 - mn0), fac1 = __expf(m1 - mn1);
        m0 = mn0; m1 = mn1;

        float rs0 = 0.f, rs1 = 0.f;
#pragma unroll
        for (int j = 0; j < 8; j++) {
            float p0 = __expf(sacc[j][0] - mn0);
            float p1 = __expf(sacc[j][1] - mn0);
            float p2 = __expf(sacc[j][2] - mn1);
            float p3 = __expf(sacc[j][3] - mn1);
            rs0 += p0 + p1; rs1 += p2 + p3;
            __nv_bfloat16 h0, h1, h2, h3, q0, q1, q2, q3;
            bsplit(p0, h0, q0); bsplit(p1, h1, q1);
            bsplit(p2, h2, q2); bsplit(p3, h3, q3);
            const int wcol = 4 * j + t;  // word index of cols 8j+2t
            Ph32[(row16 + g) * PB32 + wcol]     = pack2(h0, h1);
            Ph32[(row16 + g + 8) * PB32 + wcol] = pack2(h2, h3);
            Pl32[(row16 + g) * PB32 + wcol]     = pack2(q0, q1);
            Pl32[(row16 + g + 8) * PB32 + wcol] = pack2(q2, q3);
        }
        rs0 += __shfl_xor_sync(0xffffffffu, rs0, 1);
        rs0 += __shfl_xor_sync(0xffffffffu, rs0, 2);
        rs1 += __shfl_xor_sync(0xffffffffu, rs1, 1);
        rs1 += __shfl_xor_sync(0xffffffffu, rs1, 2);
        l0s = l0s * fac0 + rs0;
        l1s = l1s * fac1 + rs1;
#pragma unroll
        for (int j = 0; j < 8; j++) {
            oacc[j][0] *= fac0; oacc[j][1] *= fac0;
            oacc[j][2] *= fac1; oacc[j][3] *= fac1;
        }
        __syncwarp();  // P visible to this warp's mma loads

        // ---- O += P V  (bf16x3: PhVh + PhVl + PlVh) ----
#pragma unroll
        for (int kb = 0; kb < 64; kb += 16) {
            const int w0 = kb / 2 + t;
            uint32_t pfh[4], pfl[4];
            pfh[0] = Ph32[(row16 + g) * PB32 + w0];
            pfh[1] = Ph32[(row16 + g + 8) * PB32 + w0];
            pfh[2] = Ph32[(row16 + g) * PB32 + w0 + 4];
            pfh[3] = Ph32[(row16 + g + 8) * PB32 + w0 + 4];
            pfl[0] = Pl32[(row16 + g) * PB32 + w0];
            pfl[1] = Pl32[(row16 + g + 8) * PB32 + w0];
            pfl[2] = Pl32[(row16 + g) * PB32 + w0 + 4];
            pfl[3] = Pl32[(row16 + g + 8) * PB32 + w0 + 4];
#pragma unroll
            for (int j = 0; j < 8; j++) {
                uint32_t vh0 = Vh32[(j * 8 + g) * PB32 + w0];
                uint32_t vh1 = Vh32[(j * 8 + g) * PB32 + w0 + 4];
                uint32_t vl0 = Vl32[(j * 8 + g) * PB32 + w0];
                uint32_t vl1 = Vl32[(j * 8 + g) * PB32 + w0 + 4];
                mma_bf16(oacc[j], pfh, vh0, vh1);
                mma_bf16(oacc[j], pfh, vl0, vl1);
                mma_bf16(oacc[j], pfl, vh0, vh1);
            }
        }
        __syncwarp();  // P/V reads done before next tile's overwrite
    }

    // ---- Epilogue: normalize, store ----
    float inv0 = 1.f / l0s, inv1 = 1.f / l1s;
    float* Ob = O + base + (size_t)qt * 64 * D_MODEL;
#pragma unroll
    for (int j = 0; j < 8; j++) {
        int col = j * 8 + 2 * t;
        *(float2*)(Ob + (size_t)(row16 + g) * D_MODEL + col) =
            make_float2(oacc[j][0] * inv0, oacc[j][1] * inv0);
        *(float2*)(Ob + (size_t)(row16 + g + 8) * D_MODEL + col) =
            make_float2(oacc[j][2] * inv1, oacc[j][3] * inv1);
    }
}

// ---------------------------------------------------------------------------
// Launch. Input order:
// 0:q 1:k 2:v 3:W_q 4:b_q 5:W_k 6:b_k 7:W_v 8:b_v 9:W_o 10:b_o
// ---------------------------------------------------------------------------
extern "C" void kernel_launch(void* const* d_in, const int* in_sizes, int n_in,
                              void* d_out, int out_size)
{
    (void)in_sizes; (void)n_in; (void)out_size;
    const float* q   = (const float*)d_in[0];
    const float* k   = (const float*)d_in[1];
    const float* v   = (const float*)d_in[2];
    const float* W_q = (const float*)d_in[3];
    const float* b_q = (const float*)d_in[4];
    const float* W_k = (const float*)d_in[5];
    const float* b_k = (const float*)d_in[6];
    const float* W_v = (const float*)d_in[7];
    const float* b_v = (const float*)d_in[8];
    const float* W_o = (const float*)d_in[9];
    const float* b_o = (const float*)d_in[10];
    float* out = (float*)d_out;

    float *gQ, *gK, *gV, *gA;
    cudaGetSymbolAddress((void**)&gQ, g_Q);
    cudaGetSymbolAddress((void**)&gK, g_K);
    cudaGetSymbolAddress((void**)&gV, g_V);
    cudaGetSymbolAddress((void**)&gA, g_A);

    dim3 gridP(D_MODEL / BN, NTOK / BM);  // (8, 64)

    gemm_tf32_bias<<<gridP, 256>>>(q, W_q, b_q, gQ, NTOK, D_MODEL, D_MODEL);
    gemm_tf32_bias<<<gridP, 256>>>(k, W_k, b_k, gK, NTOK, D_MODEL, D_MODEL);
    gemm_tf32_bias<<<gridP, 256>>>(v, W_v, b_v, gV, NTOK, D_MODEL, D_MODEL);

    cudaFuncSetAttribute(attention_bf16x3_kernel,
                         cudaFuncAttributeMaxDynamicSharedMemorySize, ATT_SMEM);
    attention_bf16x3_kernel<<<dim3(TSEQ / 64, HEADS, BATCH), 128, ATT_SMEM>>>(gQ, gK, gV, gA);

    gemm_tf32_bias<<<gridP, 256>>>(gA, W_o, b_o, out, NTOK, D_MODEL, D_MODEL);
}

// round 7
// speedup vs baseline: 2.3272x; 1.0708x over previous
#include <cuda_runtime.h>
#include <cuda_bf16.h>
#include <math.h>
#include <stdint.h>
#include <string.h>

#define D_MODEL 1024
#define NTOK    8192   // B*T
#define HEADS   16
#define HD      64
#define TSEQ    2048
#define BATCH   4

// GEMM tiling
#define BM 128
#define BN 128
#define BKT 16
#define APAD 20
#define BPAD 136

// Attention bf16 smem pitch (bf16 elements). 72*2B=144B rows; 36 words.
#define PB   72
#define PB32 36

// Scratch (no allocation allowed — device globals). 16B-aligned.
__device__ __align__(16) float g_Q[NTOK * D_MODEL];
__device__ __align__(16) float g_K[NTOK * D_MODEL];
__device__ __align__(16) float g_V[NTOK * D_MODEL];
__device__ __align__(16) float g_A[NTOK * D_MODEL];

__device__ __forceinline__ float tf32r(float x) {
    uint32_t u;
    asm("cvt.rna.tf32.f32 %0, %1;" : "=r"(u) : "f"(x));
    return __uint_as_float(u);
}

__device__ __forceinline__ void mma_tf32(float* c, const uint32_t* a, const uint32_t* b) {
    asm volatile(
        "mma.sync.aligned.m16n8k8.row.col.f32.tf32.tf32.f32 "
        "{%0,%1,%2,%3}, {%4,%5,%6,%7}, {%8,%9}, {%0,%1,%2,%3};\n"
        : "+f"(c[0]), "+f"(c[1]), "+f"(c[2]), "+f"(c[3])
        : "r"(a[0]), "r"(a[1]), "r"(a[2]), "r"(a[3]), "r"(b[0]), "r"(b[1]));
}

__device__ __forceinline__ void mma_bf16(float* c, const uint32_t* a, uint32_t b0, uint32_t b1) {
    asm volatile(
        "mma.sync.aligned.m16n8k16.row.col.f32.bf16.bf16.f32 "
        "{%0,%1,%2,%3}, {%4,%5,%6,%7}, {%8,%9}, {%0,%1,%2,%3};\n"
        : "+f"(c[0]), "+f"(c[1]), "+f"(c[2]), "+f"(c[3])
        : "r"(a[0]), "r"(a[1]), "r"(a[2]), "r"(a[3]), "r"(b0), "r"(b1));
}

// split fp32 -> bf16 hi + bf16 lo  (hi+lo reproduces ~16 mantissa bits)
__device__ __forceinline__ void bsplit(float x, __nv_bfloat16& h, __nv_bfloat16& l) {
    h = __float2bfloat16(x);
    l = __float2bfloat16(x - __bfloat162float(h));
}

// pack two bf16 into one 32-bit word (lo in low half, hi in high half)
__device__ __forceinline__ uint32_t pack2(__nv_bfloat16 lo, __nv_bfloat16 hi) {
    __nv_bfloat162 p = __halves2bfloat162(lo, hi);
    uint32_t u;
    memcpy(&u, &p, 4);
    return u;
}

// ---------------------------------------------------------------------------
// TF32 tensor-core GEMM (unchanged from passing R5 kernel)
// ---------------------------------------------------------------------------
__global__ __launch_bounds__(256, 2)
void gemm_tf32_bias(const float* __restrict__ A, const float* __restrict__ B,
                    const float* __restrict__ bias, float* __restrict__ C,
                    int M, int N, int K)
{
    __shared__ float As[BM * APAD];
    __shared__ float Bs[BKT * BPAD];

    const int tid  = threadIdx.x;
    const int warp = tid >> 5, lane = tid & 31;
    const int g = lane >> 2, t = lane & 3;
    const int wm = (warp >> 2) * 64;
    const int wn = (warp & 3) * 32;

    const int bx = blockIdx.x, by = blockIdx.y;
    const float* Ab = A + (size_t)by * BM * K;
    const float* Bb = B + bx * BN;

    const int arow = tid >> 1, acol = (tid & 1) * 8;
    const int brow = tid >> 4, bcol = (tid & 15) * 8;

    float4 pa0 = *(const float4*)(Ab + (size_t)arow * K + acol);
    float4 pa1 = *(const float4*)(Ab + (size_t)arow * K + acol + 4);
    float4 pb0 = *(const float4*)(Bb + (size_t)brow * N + bcol);
    float4 pb1 = *(const float4*)(Bb + (size_t)brow * N + bcol + 4);

    float acc[4][4][4];
#pragma unroll
    for (int mt = 0; mt < 4; mt++)
#pragma unroll
        for (int nt = 0; nt < 4; nt++)
#pragma unroll
            for (int i = 0; i < 4; i++) acc[mt][nt][i] = 0.f;

    for (int k0 = 0; k0 < K; k0 += BKT) {
        float* ad = As + arow * APAD + acol;
        ad[0] = tf32r(pa0.x); ad[1] = tf32r(pa0.y); ad[2] = tf32r(pa0.z); ad[3] = tf32r(pa0.w);
        ad[4] = tf32r(pa1.x); ad[5] = tf32r(pa1.y); ad[6] = tf32r(pa1.z); ad[7] = tf32r(pa1.w);
        float* bd = Bs + brow * BPAD + bcol;
        bd[0] = tf32r(pb0.x); bd[1] = tf32r(pb0.y); bd[2] = tf32r(pb0.z); bd[3] = tf32r(pb0.w);
        bd[4] = tf32r(pb1.x); bd[5] = tf32r(pb1.y); bd[6] = tf32r(pb1.z); bd[7] = tf32r(pb1.w);
        __syncthreads();

        if (k0 + BKT < K) {
            pa0 = *(const float4*)(Ab + (size_t)arow * K + k0 + BKT + acol);
            pa1 = *(const float4*)(Ab + (size_t)arow * K + k0 + BKT + acol + 4);
            pb0 = *(const float4*)(Bb + (size_t)(k0 + BKT + brow) * N + bcol);
            pb1 = *(const float4*)(Bb + (size_t)(k0 + BKT + brow) * N + bcol + 4);
        }

#pragma unroll
        for (int kk = 0; kk < BKT; kk += 8) {
            uint32_t af[4][4];
#pragma unroll
            for (int mt = 0; mt < 4; mt++) {
                const float* ap = As + (wm + mt * 16 + g) * APAD + kk + t;
                af[mt][0] = __float_as_uint(ap[0]);
                af[mt][1] = __float_as_uint(ap[8 * APAD]);
                af[mt][2] = __float_as_uint(ap[4]);
                af[mt][3] = __float_as_uint(ap[8 * APAD + 4]);
            }
            uint32_t bf[4][2];
#pragma unroll
            for (int nt = 0; nt < 4; nt++) {
                const float* bp = Bs + (kk + t) * BPAD + wn + nt * 8 + g;
                bf[nt][0] = __float_as_uint(bp[0]);
                bf[nt][1] = __float_as_uint(bp[4 * BPAD]);
            }
#pragma unroll
            for (int mt = 0; mt < 4; mt++)
#pragma unroll
                for (int nt = 0; nt < 4; nt++)
                    mma_tf32(acc[mt][nt], af[mt], bf[nt]);
        }
        __syncthreads();
    }

#pragma unroll
    for (int mt = 0; mt < 4; mt++) {
        int row0 = by * BM + wm + mt * 16 + g;
#pragma unroll
        for (int nt = 0; nt < 4; nt++) {
            int col = bx * BN + wn + nt * 8 + 2 * t;
            float b0 = bias[col], b1 = bias[col + 1];
            float2 r0 = make_float2(acc[mt][nt][0] + b0, acc[mt][nt][1] + b1);
            float2 r1 = make_float2(acc[mt][nt][2] + b0, acc[mt][nt][3] + b1);
            *(float2*)(C + (size_t)row0 * N + col) = r0;
            *(float2*)(C + (size_t)(row0 + 8) * N + col) = r1;
        }
    }
}

// ---------------------------------------------------------------------------
// Flash attention, bf16x3 split MMA. P kept in registers (S-accumulator
// fragment == PV A-fragment layout). Q fragments hoisted out of the key loop.
// smem planes (pitch PB=72 bf16): Qh Ql Kh Kl Vth Vtl = 6*64*72*2 = 55296 B.
// ---------------------------------------------------------------------------
#define OFF_QH 0
#define OFF_QL (64 * PB)
#define OFF_KH (2 * 64 * PB)
#define OFF_KL (3 * 64 * PB)
#define OFF_VH (4 * 64 * PB)
#define OFF_VL (5 * 64 * PB)
#define ATT_SMEM (6 * 64 * PB * 2)   // 55296 bytes

__global__ __launch_bounds__(128, 3)
void attention_bf16x3_kernel(const float* __restrict__ Q, const float* __restrict__ K,
                             const float* __restrict__ V, float* __restrict__ O)
{
    extern __shared__ __align__(16) __nv_bfloat16 sb[];
    __nv_bfloat16* Qh = sb + OFF_QH;
    __nv_bfloat16* Ql = sb + OFF_QL;
    __nv_bfloat16* Kh = sb + OFF_KH;
    __nv_bfloat16* Kl = sb + OFF_KL;
    __nv_bfloat16* Vh = sb + OFF_VH;   // transposed [d][key]
    __nv_bfloat16* Vl = sb + OFF_VL;

    const uint32_t* Qh32 = (const uint32_t*)Qh;
    const uint32_t* Ql32 = (const uint32_t*)Ql;
    const uint32_t* Kh32 = (const uint32_t*)Kh;
    const uint32_t* Kl32 = (const uint32_t*)Kl;
    const uint32_t* Vh32 = (const uint32_t*)Vh;
    const uint32_t* Vl32 = (const uint32_t*)Vl;

    const int tid  = threadIdx.x;
    const int warp = tid >> 5, lane = tid & 31;
    const int g = lane >> 2, t = lane & 3;
    const int row16 = warp * 16;

    const int qt = blockIdx.x, h = blockIdx.y, b = blockIdx.z;
    const size_t base = ((size_t)b * TSEQ) * D_MODEL + (size_t)h * HD;
    const float* Qb = Q + base + (size_t)qt * 64 * D_MODEL;
    const float* Kb = K + base;
    const float* Vb = V + base;

    // ---- Load + scale + split Q once (64x64) ----
#pragma unroll
    for (int it = 0; it < 8; it++) {
        int i = tid + it * 128;
        int r = i >> 4, c = (i & 15) * 4;
        float4 q4 = *(const float4*)(Qb + (size_t)r * D_MODEL + c);
        __nv_bfloat16 h0, h1, h2, h3, l0, l1, l2, l3;
        bsplit(q4.x * 0.125f, h0, l0); bsplit(q4.y * 0.125f, h1, l1);
        bsplit(q4.z * 0.125f, h2, l2); bsplit(q4.w * 0.125f, h3, l3);
        *(uint32_t*)&Qh[r * PB + c]     = pack2(h0, h1);
        *(uint32_t*)&Qh[r * PB + c + 2] = pack2(h2, h3);
        *(uint32_t*)&Ql[r * PB + c]     = pack2(l0, l1);
        *(uint32_t*)&Ql[r * PB + c + 2] = pack2(l2, l3);
    }
    __syncthreads();

    // ---- Hoist Q fragments to registers (loop-invariant) ----
    uint32_t qfh[4][4], qfl[4][4];
#pragma unroll
    for (int u = 0; u < 4; u++) {
        const int w0 = u * 8 + t;
        qfh[u][0] = Qh32[(row16 + g) * PB32 + w0];
        qfh[u][1] = Qh32[(row16 + g + 8) * PB32 + w0];
        qfh[u][2] = Qh32[(row16 + g) * PB32 + w0 + 4];
        qfh[u][3] = Qh32[(row16 + g + 8) * PB32 + w0 + 4];
        qfl[u][0] = Ql32[(row16 + g) * PB32 + w0];
        qfl[u][1] = Ql32[(row16 + g + 8) * PB32 + w0];
        qfl[u][2] = Ql32[(row16 + g) * PB32 + w0 + 4];
        qfl[u][3] = Ql32[(row16 + g + 8) * PB32 + w0 + 4];
    }

    float oacc[8][4];
#pragma unroll
    for (int j = 0; j < 8; j++)
#pragma unroll
        for (int i = 0; i < 4; i++) oacc[j][i] = 0.f;
    float m0 = -1e30f, m1 = -1e30f, l0s = 0.f, l1s = 0.f;

    // V lane mapping: row = 16*warp + (lane&15), col group by (lane>>4)
    const int vrow = row16 + (lane & 15);
    const int vcg  = lane >> 4;

    for (int j0 = 0; j0 < TSEQ; j0 += 64) {
        __syncthreads();  // previous tile's K/V reads complete

        // ---- Load + split K (coalesced), V (transposed) ----
#pragma unroll
        for (int it = 0; it < 8; it++) {
            int i = tid + it * 128;
            int r = i >> 4, c = (i & 15) * 4;
            float4 k4 = *(const float4*)(Kb + (size_t)(j0 + r) * D_MODEL + c);
            __nv_bfloat16 h0, h1, h2, h3, l0, l1, l2, l3;
            bsplit(k4.x, h0, l0); bsplit(k4.y, h1, l1);
            bsplit(k4.z, h2, l2); bsplit(k4.w, h3, l3);
            *(uint32_t*)&Kh[r * PB + c]     = pack2(h0, h1);
            *(uint32_t*)&Kh[r * PB + c + 2] = pack2(h2, h3);
            *(uint32_t*)&Kl[r * PB + c]     = pack2(l0, l1);
            *(uint32_t*)&Kl[r * PB + c + 2] = pack2(l2, l3);
        }
#pragma unroll
        for (int it = 0; it < 8; it++) {
            int c = (vcg + 2 * it) * 4;
            float4 v4 = *(const float4*)(Vb + (size_t)(j0 + vrow) * D_MODEL + c);
            __nv_bfloat16 hh, ll;
            bsplit(v4.x, hh, ll); Vh[(c + 0) * PB + vrow] = hh; Vl[(c + 0) * PB + vrow] = ll;
            bsplit(v4.y, hh, ll); Vh[(c + 1) * PB + vrow] = hh; Vl[(c + 1) * PB + vrow] = ll;
            bsplit(v4.z, hh, ll); Vh[(c + 2) * PB + vrow] = hh; Vl[(c + 2) * PB + vrow] = ll;
            bsplit(v4.w, hh, ll); Vh[(c + 3) * PB + vrow] = hh; Vl[(c + 3) * PB + vrow] = ll;
        }
        __syncthreads();

        // ---- S = Q K^T  (bf16x3: QhKh + QhKl + QlKh) ----
        float sacc[8][4];
#pragma unroll
        for (int j = 0; j < 8; j++)
#pragma unroll
            for (int i = 0; i < 4; i++) sacc[j][i] = 0.f;

#pragma unroll
        for (int u = 0; u < 4; u++) {
            const int w0 = u * 8 + t;
#pragma unroll
            for (int j = 0; j < 8; j++) {
                uint32_t kh0 = Kh32[(j * 8 + g) * PB32 + w0];
                uint32_t kh1 = Kh32[(j * 8 + g) * PB32 + w0 + 4];
                uint32_t kl0 = Kl32[(j * 8 + g) * PB32 + w0];
                uint32_t kl1 = Kl32[(j * 8 + g) * PB32 + w0 + 4];
                mma_bf16(sacc[j], qfh[u], kh0, kh1);
                mma_bf16(sacc[j], qfh[u], kl0, kl1);
                mma_bf16(sacc[j], qfl[u], kh0, kh1);
            }
        }

        // ---- Online softmax on fragments (rows g and g+8) ----
        float mx0 = -1e30f, mx1 = -1e30f;
#pragma unroll
        for (int j = 0; j < 8; j++) {
            mx0 = fmaxf(mx0, fmaxf(sacc[j][0], sacc[j][1]));
            mx1 = fmaxf(mx1, fmaxf(sacc[j][2], sacc[j][3]));
        }
        mx0 = fmaxf(mx0, __shfl_xor_sync(0xffffffffu, mx0, 1));
        mx0 = fmaxf(mx0, __shfl_xor_sync(0xffffffffu, mx0, 2));
        mx1 = fmaxf(mx1, __shfl_xor_sync(0xffffffffu, mx1, 1));
        mx1 = fmaxf(mx1, __shfl_xor_sync(0xffffffffu, mx1, 2));

        float mn0 = fmaxf(m0, mx0), mn1 = fmaxf(m1, mx1);
        float fac0 = __expf(m0 - mn0), fac1 = __expf(m1 - mn1);
        m0 = mn0; m1 = mn1;

        // P packs (registers): A-fragment halves for the PV mma
        uint32_t ph01[8], ph23[8], pl01[8], pl23[8];
        float rs0 = 0.f, rs1 = 0.f;
#pragma unroll
        for (int j = 0; j < 8; j++) {
            float p0 = __expf(sacc[j][0] - mn0);
            float p1 = __expf(sacc[j][1] - mn0);
            float p2 = __expf(sacc[j][2] - mn1);
            float p3 = __expf(sacc[j][3] - mn1);
            rs0 += p0 + p1; rs1 += p2 + p3;
            __nv_bfloat16 h0, h1, h2, h3, q0, q1, q2, q3;
            bsplit(p0, h0, q0); bsplit(p1, h1, q1);
            bsplit(p2, h2, q2); bsplit(p3, h3, q3);
            ph01[j] = pack2(h0, h1);
            ph23[j] = pack2(h2, h3);
            pl01[j] = pack2(q0, q1);
            pl23[j] = pack2(q2, q3);
        }
        rs0 += __shfl_xor_sync(0xffffffffu, rs0, 1);
        rs0 += __shfl_xor_sync(0xffffffffu, rs0, 2);
        rs1 += __shfl_xor_sync(0xffffffffu, rs1, 1);
        rs1 += __shfl_xor_sync(0xffffffffu, rs1, 2);
        l0s = l0s * fac0 + rs0;
        l1s = l1s * fac1 + rs1;
#pragma unroll
        for (int j = 0; j < 8; j++) {
            oacc[j][0] *= fac0; oacc[j][1] *= fac0;
            oacc[j][2] *= fac1; oacc[j][3] *= fac1;
        }

        // ---- O += P V  (bf16x3: PhVh + PhVl + PlVh), P from registers ----
#pragma unroll
        for (int u = 0; u < 4; u++) {
            const int w0 = u * 8 + t;
            uint32_t pfh[4] = { ph01[2 * u], ph23[2 * u], ph01[2 * u + 1], ph23[2 * u + 1] };
            uint32_t pfl[4] = { pl01[2 * u], pl23[2 * u], pl01[2 * u + 1], pl23[2 * u + 1] };
#pragma unroll
            for (int j = 0; j < 8; j++) {
                uint32_t vh0 = Vh32[(j * 8 + g) * PB32 + w0];
                uint32_t vh1 = Vh32[(j * 8 + g) * PB32 + w0 + 4];
                uint32_t vl0 = Vl32[(j * 8 + g) * PB32 + w0];
                uint32_t vl1 = Vl32[(j * 8 + g) * PB32 + w0 + 4];
                mma_bf16(oacc[j], pfh, vh0, vh1);
                mma_bf16(oacc[j], pfh, vl0, vl1);
                mma_bf16(oacc[j], pfl, vh0, vh1);
            }
        }
    }

    // ---- Epilogue: normalize, store ----
    float inv0 = 1.f / l0s, inv1 = 1.f / l1s;
    float* Ob = O + base + (size_t)qt * 64 * D_MODEL;
#pragma unroll
    for (int j = 0; j < 8; j++) {
        int col = j * 8 + 2 * t;
        *(float2*)(Ob + (size_t)(row16 + g) * D_MODEL + col) =
            make_float2(oacc[j][0] * inv0, oacc[j][1] * inv0);
        *(float2*)(Ob + (size_t)(row16 + g + 8) * D_MODEL + col) =
            make_float2(oacc[j][2] * inv1, oacc[j][3] * inv1);
    }
}

// ---------------------------------------------------------------------------
// Launch. Input order:
// 0:q 1:k 2:v 3:W_q 4:b_q 5:W_k 6:b_k 7:W_v 8:b_v 9:W_o 10:b_o
// ---------------------------------------------------------------------------
extern "C" void kernel_launch(void* const* d_in, const int* in_sizes, int n_in,
                              void* d_out, int out_size)
{
    (void)in_sizes; (void)n_in; (void)out_size;
    const float* q   = (const float*)d_in[0];
    const float* k   = (const float*)d_in[1];
    const float* v   = (const float*)d_in[2];
    const float* W_q = (const float*)d_in[3];
    const float* b_q = (const float*)d_in[4];
    const float* W_k = (const float*)d_in[5];
    const float* b_k = (const float*)d_in[6];
    const float* W_v = (const float*)d_in[7];
    const float* b_v = (const float*)d_in[8];
    const float* W_o = (const float*)d_in[9];
    const float* b_o = (const float*)d_in[10];
    float* out = (float*)d_out;

    float *gQ, *gK, *gV, *gA;
    cudaGetSymbolAddress((void**)&gQ, g_Q);
    cudaGetSymbolAddress((void**)&gK, g_K);
    cudaGetSymbolAddress((void**)&gV, g_V);
    cudaGetSymbolAddress((void**)&gA, g_A);

    dim3 gridP(D_MODEL / BN, NTOK / BM);  // (8, 64)

    gemm_tf32_bias<<<gridP, 256>>>(q, W_q, b_q, gQ, NTOK, D_MODEL, D_MODEL);
    gemm_tf32_bias<<<gridP, 256>>>(k, W_k, b_k, gK, NTOK, D_MODEL, D_MODEL);
    gemm_tf32_bias<<<gridP, 256>>>(v, W_v, b_v, gV, NTOK, D_MODEL, D_MODEL);

    cudaFuncSetAttribute(attention_bf16x3_kernel,
                         cudaFuncAttributeMaxDynamicSharedMemorySize, ATT_SMEM);
    attention_bf16x3_kernel<<<dim3(TSEQ / 64, HEADS, BATCH), 128, ATT_SMEM>>>(gQ, gK, gV, gA);

    gemm_tf32_bias<<<gridP, 256>>>(gA, W_o, b_o, out, NTOK, D_MODEL, D_MODEL);
}